// round 1
// baseline (speedup 1.0000x reference)
#include <cuda_runtime.h>
#include <cuda_bf16.h>
#include <cstdint>
#include <cstddef>

// Problem constants
#define Bn   16
#define Ln   1024
#define DIMn 1024
#define NH   16
#define DK   64

#define OUT_ELEMS    (16*1024*1024)          // 16777216
#define ATTNS_ELEMS  (16*8*1024*1024)        // 134217728
#define ATTNF_ELEMS  (16*8*64*64)            // 524288

// Scratch: head-major Qh/Kh/Vh [B][H][L][64] and concat buffer [B*L][1024]
__device__ float g_qh[OUT_ELEMS];
__device__ float g_kh[OUT_ELEMS];
__device__ float g_vh[OUT_ELEMS];
__device__ float g_cat[OUT_ELEMS];

// ---------------------------------------------------------------------------
// SGEMM: C = A(MxK) @ B(KxN), fp32, BM=BN=128, BK=8, 256 threads, 8x8/thread.
// MODE 0: plain row-major store. MODE 1: head-major store
//         C[((b*16+h)*1024 + l)*64 + d] with b=row/1024, l=row%1024, h=col/64.
// ---------------------------------------------------------------------------
#define BM 128
#define BN 128
#define BK 8
template<int MODE>
__global__ __launch_bounds__(256) void sgemm_k(
    const float* __restrict__ A, const float* __restrict__ B,
    float* __restrict__ C, int M, int N, int K)
{
    __shared__ float As[BK][BM];
    __shared__ float Bs[BK][BN];
    const int tid  = threadIdx.x;
    const int bm   = blockIdx.y, bn = blockIdx.x;
    const int row0 = bm * BM, col0 = bn * BN;

    const int tr = (tid >> 4) * 8;   // 0..120
    const int tc = (tid & 15) * 8;   // 0..120

    float acc[8][8];
    #pragma unroll
    for (int i = 0; i < 8; i++)
        #pragma unroll
        for (int j = 0; j < 8; j++) acc[i][j] = 0.f;

    const int arow = tid >> 1;            // 0..127
    const int acol = (tid & 1) * 4;       // 0 or 4
    const int brow = tid >> 5;            // 0..7
    const int bcol = (tid & 31) * 4;      // 0..124
    const float* Aptr = A + (size_t)(row0 + arow) * K + acol;
    const float* Bptr = B + (size_t)brow * N + col0 + bcol;

    for (int k0 = 0; k0 < K; k0 += BK) {
        float4 av = *(const float4*)(Aptr + k0);
        float4 bv = *(const float4*)(Bptr + (size_t)k0 * N);
        As[acol + 0][arow] = av.x;
        As[acol + 1][arow] = av.y;
        As[acol + 2][arow] = av.z;
        As[acol + 3][arow] = av.w;
        *(float4*)&Bs[brow][bcol] = bv;
        __syncthreads();

        #pragma unroll
        for (int k = 0; k < BK; k++) {
            float4 a0 = *(const float4*)&As[k][tr];
            float4 a1 = *(const float4*)&As[k][tr + 4];
            float4 b0 = *(const float4*)&Bs[k][tc];
            float4 b1 = *(const float4*)&Bs[k][tc + 4];
            float a[8] = {a0.x, a0.y, a0.z, a0.w, a1.x, a1.y, a1.z, a1.w};
            float b[8] = {b0.x, b0.y, b0.z, b0.w, b1.x, b1.y, b1.z, b1.w};
            #pragma unroll
            for (int i = 0; i < 8; i++)
                #pragma unroll
                for (int j = 0; j < 8; j++)
                    acc[i][j] = fmaf(a[i], b[j], acc[i][j]);
        }
        __syncthreads();
    }

    #pragma unroll
    for (int i = 0; i < 8; i++) {
        int r = row0 + tr + i;
        float4 v0 = make_float4(acc[i][0], acc[i][1], acc[i][2], acc[i][3]);
        float4 v1 = make_float4(acc[i][4], acc[i][5], acc[i][6], acc[i][7]);
        if (MODE == 0) {
            float* cp = C + (size_t)r * N + col0 + tc;
            *(float4*)cp       = v0;
            *(float4*)(cp + 4) = v1;
        } else {
            int b_ = r >> 10, l_ = r & 1023;
            int c  = col0 + tc;
            int h_ = c >> 6, d_ = c & 63;
            float* cp = C + (((size_t)(b_ * 16 + h_) * 1024 + l_) * 64 + d_);
            *(float4*)cp       = v0;
            *(float4*)(cp + 4) = v1;
        }
    }
}

// ---------------------------------------------------------------------------
// Even-head attention. Block = (qtile 32 rows, head-slot j (orig head 2j), b).
// smem: S[32][1024] fp32, Q[32][64], K/V tiles [64][68].
// Writes attn_s (normalized) and out_cat cols [j*64, j*64+64).
// ---------------------------------------------------------------------------
#define KPAD 68
#define SMEM_EVEN ((32*1024 + 32*64 + 2*64*KPAD) * 4)
__global__ __launch_bounds__(256) void attn_even_k(
    const float* __restrict__ Qh, const float* __restrict__ Kh,
    const float* __restrict__ Vh, const float* __restrict__ mask_s,
    float* __restrict__ attn_s, float* __restrict__ out_cat)
{
    extern __shared__ float sm[];
    float* Ssm = sm;                       // 32*1024
    float* Qs  = Ssm + 32 * 1024;          // 32*64
    float* Ks  = Qs + 32 * 64;             // 64*KPAD
    float* Vs  = Ks + 64 * KPAD;           // 64*KPAD

    const int qt = blockIdx.x, j = blockIdx.y, b = blockIdx.z;
    const int h = 2 * j;
    const int tid = threadIdx.x;
    const size_t headoff = (size_t)(b * 16 + h) * 1024 * 64;
    const float* Qb = Qh + headoff;
    const float* Kb = Kh + headoff;
    const float* Vb = Vh + headoff;
    const int r0 = qt * 32;

    // Load Q tile (32x64, contiguous)
    for (int i = tid; i < 512; i += 256)
        ((float4*)Qs)[i] = ((const float4*)(Qb + (size_t)r0 * 64))[i];

    const int col  = tid & 63;   // K-seq index within tile / d-index for outputs
    const int rgrp = tid >> 6;   // 0..3

    // ---- S = Q Kᵀ over 16 K tiles ----
    for (int kt = 0; kt < 16; kt++) {
        __syncthreads();
        for (int i = tid; i < 1024; i += 256) {   // 1024 float4
            float4 v = ((const float4*)(Kb + (size_t)kt * 4096))[i];
            int rr = i >> 4, cc = (i & 15) << 2;
            *(float4*)&Ks[rr * KPAD + cc] = v;
        }
        __syncthreads();

        float accS[8];
        #pragma unroll
        for (int i = 0; i < 8; i++) accS[i] = 0.f;

        for (int d0 = 0; d0 < 64; d0 += 4) {
            float4 kv = *(const float4*)&Ks[col * KPAD + d0];
            #pragma unroll
            for (int i = 0; i < 8; i++) {
                float4 qv = *(const float4*)&Qs[(rgrp + 4 * i) * 64 + d0];
                accS[i] = fmaf(qv.x, kv.x, accS[i]);
                accS[i] = fmaf(qv.y, kv.y, accS[i]);
                accS[i] = fmaf(qv.z, kv.z, accS[i]);
                accS[i] = fmaf(qv.w, kv.w, accS[i]);
            }
        }
        #pragma unroll
        for (int i = 0; i < 8; i++)
            Ssm[(rgrp + 4 * i) * 1024 + kt * 64 + col] = accS[i];
    }
    __syncthreads();

    // ---- softmax: 8 warps x 4 rows ----
    const int warp = tid >> 5, lane = tid & 31;
    for (int rr = warp * 4; rr < warp * 4 + 4; rr++) {
        const int grow = r0 + rr;
        float* Srow = Ssm + rr * 1024;
        const float* mrow = mask_s + (size_t)grow * 1024;
        float mx = -1e30f;
        for (int c = lane; c < 1024; c += 32) {
            float s = Srow[c] * 0.125f + mrow[c];
            Srow[c] = s;
            mx = fmaxf(mx, s);
        }
        #pragma unroll
        for (int o = 16; o > 0; o >>= 1) mx = fmaxf(mx, __shfl_xor_sync(0xffffffffu, mx, o));
        float sum = 0.f;
        for (int c = lane; c < 1024; c += 32) {
            float e = __expf(Srow[c] - mx);
            Srow[c] = e;
            sum += e;
        }
        #pragma unroll
        for (int o = 16; o > 0; o >>= 1) sum += __shfl_xor_sync(0xffffffffu, sum, o);
        float inv = 1.f / sum;
        float* arow = attn_s + ((size_t)(b * 8 + j) * 1024 + grow) * 1024;
        for (int c = lane; c < 1024; c += 32) {
            float p = Srow[c] * inv;
            Srow[c] = p;
            arow[c] = p;
        }
    }
    __syncthreads();

    // ---- O = P V over 16 V tiles ----
    float accO[8];
    #pragma unroll
    for (int i = 0; i < 8; i++) accO[i] = 0.f;

    for (int kt = 0; kt < 16; kt++) {
        __syncthreads();
        for (int i = tid; i < 1024; i += 256) {
            float4 v = ((const float4*)(Vb + (size_t)kt * 4096))[i];
            int rr = i >> 4, cc = (i & 15) << 2;
            *(float4*)&Vs[rr * KPAD + cc] = v;
        }
        __syncthreads();

        for (int k0 = 0; k0 < 64; k0 += 4) {
            float v0 = Vs[(k0 + 0) * KPAD + col];
            float v1 = Vs[(k0 + 1) * KPAD + col];
            float v2 = Vs[(k0 + 2) * KPAD + col];
            float v3 = Vs[(k0 + 3) * KPAD + col];
            #pragma unroll
            for (int i = 0; i < 8; i++) {
                float4 p = *(const float4*)&Ssm[(rgrp + 4 * i) * 1024 + kt * 64 + k0];
                accO[i] = fmaf(p.x, v0, accO[i]);
                accO[i] = fmaf(p.y, v1, accO[i]);
                accO[i] = fmaf(p.z, v2, accO[i]);
                accO[i] = fmaf(p.w, v3, accO[i]);
            }
        }
    }
    #pragma unroll
    for (int i = 0; i < 8; i++) {
        int row = rgrp + 4 * i;
        out_cat[((size_t)b * 1024 + r0 + row) * 1024 + j * 64 + col] = accO[i];
    }
}

// ---------------------------------------------------------------------------
// Odd-head "feature" attention. Block = (jp, b); orig head h = 2*jp+1.
// S_f[n][m] = (1/8) * sum_l Qh[l][n]*Kh[l][m]; softmax over m; attn_f out.
// out[l][n]  = sum_m Vh[l][m] * A[n][m]  -> out_cat cols [(8+jp)*64, +64)
// ---------------------------------------------------------------------------
#define SMEM_FEAT ((2*64*64 + 64*65) * 4)
__global__ __launch_bounds__(256) void attn_feat_k(
    const float* __restrict__ Qh, const float* __restrict__ Kh,
    const float* __restrict__ Vh, const float* __restrict__ mask_f,
    float* __restrict__ attn_f, float* __restrict__ out_cat)
{
    extern __shared__ float sm[];
    float* Qt  = sm;              // 64*64 (reused as Vt in phase 2)
    float* Kt  = Qt + 4096;       // 64*64
    float* Asm = Kt + 4096;       // 64*65

    const int jp = blockIdx.x, b = blockIdx.y;
    const int h = 2 * jp + 1;
    const int tid = threadIdx.x;
    const size_t headoff = (size_t)(b * 16 + h) * 1024 * 64;
    const float* Qb = Qh + headoff;
    const float* Kb = Kh + headoff;
    const float* Vb = Vh + headoff;

    const int m  = tid & 63;
    const int g4 = tid >> 6;   // 0..3

    float acc[16];
    #pragma unroll
    for (int i = 0; i < 16; i++) acc[i] = 0.f;

    // ---- phase 1: S_f accumulation over 16 L-tiles ----
    for (int lt = 0; lt < 16; lt++) {
        __syncthreads();
        for (int i = tid; i < 1024; i += 256) {
            ((float4*)Qt)[i] = ((const float4*)(Qb + (size_t)lt * 4096))[i];
            ((float4*)Kt)[i] = ((const float4*)(Kb + (size_t)lt * 4096))[i];
        }
        __syncthreads();
        for (int ll = 0; ll < 64; ll++) {
            float kk = Kt[ll * 64 + m];
            #pragma unroll
            for (int i = 0; i < 16; i++)
                acc[i] = fmaf(Qt[ll * 64 + g4 + 4 * i], kk, acc[i]);
        }
    }
    __syncthreads();
    #pragma unroll
    for (int i = 0; i < 16; i++) {
        int n = g4 + 4 * i;
        Asm[n * 65 + m] = acc[i] * 0.125f + mask_f[n * 64 + m];
    }
    __syncthreads();

    // ---- softmax: 8 warps x 8 rows, 2 cols/lane ----
    const int warp = tid >> 5, lane = tid & 31;
    for (int n = warp * 8; n < warp * 8 + 8; n++) {
        float* row = Asm + n * 65;
        float a0 = row[lane], a1 = row[lane + 32];
        float mx = fmaxf(a0, a1);
        #pragma unroll
        for (int o = 16; o > 0; o >>= 1) mx = fmaxf(mx, __shfl_xor_sync(0xffffffffu, mx, o));
        float e0 = __expf(a0 - mx), e1 = __expf(a1 - mx);
        float s = e0 + e1;
        #pragma unroll
        for (int o = 16; o > 0; o >>= 1) s += __shfl_xor_sync(0xffffffffu, s, o);
        float inv = 1.f / s;
        e0 *= inv; e1 *= inv;
        row[lane] = e0; row[lane + 32] = e1;
        float* grow = attn_f + ((size_t)(b * 8 + jp) * 64 + n) * 64;
        grow[lane] = e0; grow[lane + 32] = e1;
    }
    __syncthreads();

    // ---- phase 2: O[l][n] = sum_m V[l][m] * A[n][m] ----
    float* Vt = Qt;   // reuse
    const int n2 = m;
    for (int lt = 0; lt < 16; lt++) {
        __syncthreads();
        for (int i = tid; i < 1024; i += 256)
            ((float4*)Vt)[i] = ((const float4*)(Vb + (size_t)lt * 4096))[i];
        __syncthreads();

        float accO[16];
        #pragma unroll
        for (int i = 0; i < 16; i++) accO[i] = 0.f;
        for (int mm = 0; mm < 64; mm++) {
            float aa = Asm[n2 * 65 + mm];
            #pragma unroll
            for (int i = 0; i < 16; i++)
                accO[i] = fmaf(Vt[(g4 + 4 * i) * 64 + mm], aa, accO[i]);
        }
        #pragma unroll
        for (int i = 0; i < 16; i++) {
            int ll = g4 + 4 * i;
            out_cat[((size_t)b * 1024 + lt * 64 + ll) * 1024 + (8 + jp) * 64 + n2] = accO[i];
        }
    }
}

// ---------------------------------------------------------------------------
extern "C" void kernel_launch(void* const* d_in, const int* in_sizes, int n_in,
                              void* d_out, int out_size)
{
    const float* q      = (const float*)d_in[0];
    const float* k      = (const float*)d_in[1];
    const float* v      = (const float*)d_in[2];
    const float* mask_s = (const float*)d_in[3];
    const float* mask_f = (const float*)d_in[4];
    const float* Wq     = (const float*)d_in[5];
    const float* Wk     = (const float*)d_in[6];
    const float* Wv     = (const float*)d_in[7];
    const float* Wo     = (const float*)d_in[8];

    float* out    = (float*)d_out;
    float* attn_s = out + OUT_ELEMS;
    float* attn_f = attn_s + ATTNS_ELEMS;

    float *qh, *kh, *vh, *cat;
    cudaGetSymbolAddress((void**)&qh,  g_qh);
    cudaGetSymbolAddress((void**)&kh,  g_kh);
    cudaGetSymbolAddress((void**)&vh,  g_vh);
    cudaGetSymbolAddress((void**)&cat, g_cat);

    cudaFuncSetAttribute(attn_even_k, cudaFuncAttributeMaxDynamicSharedMemorySize, SMEM_EVEN);
    cudaFuncSetAttribute(attn_feat_k, cudaFuncAttributeMaxDynamicSharedMemorySize, SMEM_FEAT);

    const int M = Bn * Ln;   // 16384
    dim3 gemm_grid(DIMn / BN, M / BM);   // (8, 128)

    sgemm_k<1><<<gemm_grid, 256>>>(q, Wq, qh, M, DIMn, DIMn);
    sgemm_k<1><<<gemm_grid, 256>>>(k, Wk, kh, M, DIMn, DIMn);
    sgemm_k<1><<<gemm_grid, 256>>>(v, Wv, vh, M, DIMn, DIMn);

    attn_even_k<<<dim3(32, 8, 16), 256, SMEM_EVEN>>>(qh, kh, vh, mask_s, attn_s, cat);
    attn_feat_k<<<dim3(8, 16), 256, SMEM_FEAT>>>(qh, kh, vh, mask_f, attn_f, cat);

    sgemm_k<0><<<gemm_grid, 256>>>(cat, Wo, out, M, DIMn, DIMn);
}

// round 3
// speedup vs baseline: 1.4493x; 1.4493x over previous
#include <cuda_runtime.h>
#include <cuda_bf16.h>
#include <cstdint>
#include <cstddef>

// Problem constants
#define Bn   16
#define Ln   1024
#define DIMn 1024
#define NH   16
#define DK   64

#define OUT_ELEMS    (16*1024*1024)
#define ATTNS_ELEMS  (16*8*1024*1024)
#define ATTNF_ELEMS  (16*8*64*64)

// fp32 scratch (head-major Qh/Kh/Vh, concat buffer)
__device__ float g_qh[OUT_ELEMS];
__device__ float g_kh[OUT_ELEMS];
__device__ float g_vh[OUT_ELEMS];
__device__ float g_cat[OUT_ELEMS];
// bf16 split scratch (reused across the 4 GEMMs)
__device__ __nv_bfloat16 g_ahi[OUT_ELEMS];
__device__ __nv_bfloat16 g_alo[OUT_ELEMS];
__device__ __nv_bfloat16 g_whi[DIMn*DIMn];
__device__ __nv_bfloat16 g_wlo[DIMn*DIMn];

// ===========================================================================
// Split kernels: fp32 -> bf16 hi + bf16 lo (Dekker 2-term)
// ===========================================================================
__global__ __launch_bounds__(256) void split_a_k(
    const float* __restrict__ X, __nv_bfloat16* __restrict__ hi,
    __nv_bfloat16* __restrict__ lo)
{
    int i = (blockIdx.x * 256 + threadIdx.x) * 4;
    float4 v = *(const float4*)(X + i);
    float x[4] = {v.x, v.y, v.z, v.w};
    __nv_bfloat16 h[4], l[4];
    #pragma unroll
    for (int j = 0; j < 4; j++) {
        h[j] = __float2bfloat16(x[j]);
        l[j] = __float2bfloat16(x[j] - __bfloat162float(h[j]));
    }
    __nv_bfloat162* hp = (__nv_bfloat162*)(hi + i);
    __nv_bfloat162* lp = (__nv_bfloat162*)(lo + i);
    hp[0] = __nv_bfloat162{h[0], h[1]}; hp[1] = __nv_bfloat162{h[2], h[3]};
    lp[0] = __nv_bfloat162{l[0], l[1]}; lp[1] = __nv_bfloat162{l[2], l[3]};
}

// Weight split + transpose: W[K][N] fp32 -> Wt_hi/lo[N][K] bf16
__global__ __launch_bounds__(256) void split_w_k(
    const float* __restrict__ W, __nv_bfloat16* __restrict__ hi,
    __nv_bfloat16* __restrict__ lo)
{
    __shared__ float t[32][33];
    const int tx = threadIdx.x, ty = threadIdx.y;
    const int n0 = blockIdx.x * 32, k0 = blockIdx.y * 32;
    #pragma unroll
    for (int j = 0; j < 32; j += 8)
        t[ty + j][tx] = W[(size_t)(k0 + ty + j) * DIMn + n0 + tx];
    __syncthreads();
    #pragma unroll
    for (int j = 0; j < 32; j += 8) {
        int n = n0 + ty + j, kk = k0 + tx;
        float x = t[tx][ty + j];
        __nv_bfloat16 h = __float2bfloat16(x);
        __nv_bfloat16 l = __float2bfloat16(x - __bfloat162float(h));
        hi[(size_t)n * DIMn + kk] = h;
        lo[(size_t)n * DIMn + kk] = l;
    }
}

// ===========================================================================
// Split-bf16 tensor-core GEMM: C(fp32) = A @ B, via hi/lo bf16 operands.
// A[M][K] row-major (k contig), Bt[N][K] (k contig). Block 128x128x16,
// 8 warps (2x4), warp 64x32, mma m16n8k16: acc += Ah*Bh + Ah*Bl + Al*Bh.
// Tiles in smem: [128 rows][24 bf16] (48B stride, conflict-free LDS.32).
// MODE 0: row-major C; MODE 1: head-major C.
// ===========================================================================
#define TSTR 24                    // bf16 per smem row
#define TILE_BYTES (128*TSTR*2)    // 6144
#define TILE_WORDS (128*TSTR/2)    // 1536

#define CP_ASYNC16(dst, src) \
    asm volatile("cp.async.cg.shared.global [%0], [%1], 16;\n" :: "r"(dst), "l"(src))
#define CP_COMMIT() asm volatile("cp.async.commit_group;\n" ::: "memory")
#define CP_WAIT(n)  asm volatile("cp.async.wait_group %0;\n" :: "n"(n) : "memory")

__device__ __forceinline__ void mma_bf16(float c[4], const uint32_t a[4], const uint32_t b[2]) {
    asm volatile(
        "mma.sync.aligned.m16n8k16.row.col.f32.bf16.bf16.f32 "
        "{%0,%1,%2,%3}, {%4,%5,%6,%7}, {%8,%9}, {%0,%1,%2,%3};\n"
        : "+f"(c[0]), "+f"(c[1]), "+f"(c[2]), "+f"(c[3])
        : "r"(a[0]), "r"(a[1]), "r"(a[2]), "r"(a[3]), "r"(b[0]), "r"(b[1]));
}

template<int MODE>
__global__ __launch_bounds__(256, 2) void gemm_bf16s_k(
    const __nv_bfloat16* __restrict__ Ahi, const __nv_bfloat16* __restrict__ Alo,
    const __nv_bfloat16* __restrict__ Bhi, const __nv_bfloat16* __restrict__ Blo,
    float* __restrict__ C, int M, int N, int K)
{
    __shared__ __nv_bfloat16 SM[2][4][128 * TSTR];   // 48 KB

    const int tid  = threadIdx.x;
    const int lane = tid & 31;
    const int warp = tid >> 5;
    const int wm   = warp >> 2;    // 0..1
    const int wn   = warp & 3;     // 0..3
    const int g    = lane >> 2;    // 0..7
    const int t    = lane & 3;     // 0..3

    const int row0 = blockIdx.y * 128;
    const int col0 = blockIdx.x * 128;

    uint32_t smbase;
    asm("{ .reg .u64 u; cvta.to.shared.u64 u, %1; cvt.u32.u64 %0, u; }"
        : "=r"(smbase) : "l"(&SM[0][0][0]));
    const uint32_t* sw = (const uint32_t*)&SM[0][0][0];

    const int r_ld = tid >> 1, hf = tid & 1;
    const size_t offA = ((size_t)(row0 + r_ld) * K + hf * 8) * 2;
    const size_t offB = ((size_t)(col0 + r_ld) * K + hf * 8) * 2;
    const uint32_t dloc = (uint32_t)(r_ld * 48 + hf * 16);

    auto prefetch = [&](int kt, int stage) {
        size_t kb = (size_t)kt * 32;   // kt*16 elems * 2B
        uint32_t sb = smbase + stage * (4 * TILE_BYTES) + dloc;
        CP_ASYNC16(sb + 0 * TILE_BYTES, (const char*)Ahi + offA + kb);
        CP_ASYNC16(sb + 1 * TILE_BYTES, (const char*)Alo + offA + kb);
        CP_ASYNC16(sb + 2 * TILE_BYTES, (const char*)Bhi + offB + kb);
        CP_ASYNC16(sb + 3 * TILE_BYTES, (const char*)Blo + offB + kb);
    };

    float acc[4][4][4];
    #pragma unroll
    for (int mt = 0; mt < 4; mt++)
        #pragma unroll
        for (int nt = 0; nt < 4; nt++)
            #pragma unroll
            for (int i = 0; i < 4; i++) acc[mt][nt][i] = 0.f;

    const int nk = K / 16;
    prefetch(0, 0);
    CP_COMMIT();

    for (int kt = 0; kt < nk; kt++) {
        const int stage = kt & 1;
        if (kt + 1 < nk) {
            prefetch(kt + 1, stage ^ 1);
            CP_COMMIT();
            CP_WAIT(1);
        } else {
            CP_WAIT(0);
        }
        __syncthreads();

        const int wb = stage * 4 * TILE_WORDS;

        // B fragments: hi/lo, 4 ntiles
        uint32_t bh[4][2], bl[4][2];
        #pragma unroll
        for (int nt = 0; nt < 4; nt++) {
            int rb = (wn * 32 + nt * 8 + g) * (TSTR / 2) + t;
            bh[nt][0] = sw[wb + 2 * TILE_WORDS + rb];
            bh[nt][1] = sw[wb + 2 * TILE_WORDS + rb + 4];
            bl[nt][0] = sw[wb + 3 * TILE_WORDS + rb];
            bl[nt][1] = sw[wb + 3 * TILE_WORDS + rb + 4];
        }

        #pragma unroll
        for (int mt = 0; mt < 4; mt++) {
            int ra0 = (wm * 64 + mt * 16 + g) * (TSTR / 2) + t;
            int ra1 = ra0 + 8 * (TSTR / 2);
            uint32_t ah[4], al[4];
            ah[0] = sw[wb + ra0];     ah[1] = sw[wb + ra1];
            ah[2] = sw[wb + ra0 + 4]; ah[3] = sw[wb + ra1 + 4];
            al[0] = sw[wb + TILE_WORDS + ra0];     al[1] = sw[wb + TILE_WORDS + ra1];
            al[2] = sw[wb + TILE_WORDS + ra0 + 4]; al[3] = sw[wb + TILE_WORDS + ra1 + 4];
            #pragma unroll
            for (int nt = 0; nt < 4; nt++) {
                mma_bf16(acc[mt][nt], ah, bh[nt]);
                mma_bf16(acc[mt][nt], ah, bl[nt]);
                mma_bf16(acc[mt][nt], al, bh[nt]);
            }
        }
        __syncthreads();
    }

    // Epilogue
    #pragma unroll
    for (int mt = 0; mt < 4; mt++) {
        #pragma unroll
        for (int nt = 0; nt < 4; nt++) {
            int r = row0 + wm * 64 + mt * 16 + g;
            int c = col0 + wn * 32 + nt * 8 + 2 * t;
            float2 v0 = make_float2(acc[mt][nt][0], acc[mt][nt][1]);
            float2 v1 = make_float2(acc[mt][nt][2], acc[mt][nt][3]);
            if (MODE == 0) {
                *(float2*)(C + (size_t)r * N + c)       = v0;
                *(float2*)(C + (size_t)(r + 8) * N + c) = v1;
            } else {
                int b_  = r >> 10, l0 = r & 1023;
                int h_  = c >> 6,  d_ = c & 63;
                size_t base = ((size_t)(b_ * 16 + h_) * 1024) * 64 + d_;
                *(float2*)(C + base + (size_t)l0 * 64)       = v0;
                *(float2*)(C + base + (size_t)(l0 + 8) * 64) = v1;
            }
        }
    }
}

// ---------------------------------------------------------------------------
// Even-head attention (unchanged from passing R1 kernel).
// ---------------------------------------------------------------------------
#define KPAD 68
#define SMEM_EVEN ((32*1024 + 32*64 + 2*64*KPAD) * 4)
__global__ __launch_bounds__(256) void attn_even_k(
    const float* __restrict__ Qh, const float* __restrict__ Kh,
    const float* __restrict__ Vh, const float* __restrict__ mask_s,
    float* __restrict__ attn_s, float* __restrict__ out_cat)
{
    extern __shared__ float sm[];
    float* Ssm = sm;
    float* Qs  = Ssm + 32 * 1024;
    float* Ks  = Qs + 32 * 64;
    float* Vs  = Ks + 64 * KPAD;

    const int qt = blockIdx.x, j = blockIdx.y, b = blockIdx.z;
    const int h = 2 * j;
    const int tid = threadIdx.x;
    const size_t headoff = (size_t)(b * 16 + h) * 1024 * 64;
    const float* Qb = Qh + headoff;
    const float* Kb = Kh + headoff;
    const float* Vb = Vh + headoff;
    const int r0 = qt * 32;

    for (int i = tid; i < 512; i += 256)
        ((float4*)Qs)[i] = ((const float4*)(Qb + (size_t)r0 * 64))[i];

    const int col  = tid & 63;
    const int rgrp = tid >> 6;

    for (int kt = 0; kt < 16; kt++) {
        __syncthreads();
        for (int i = tid; i < 1024; i += 256) {
            float4 v = ((const float4*)(Kb + (size_t)kt * 4096))[i];
            int rr = i >> 4, cc = (i & 15) << 2;
            *(float4*)&Ks[rr * KPAD + cc] = v;
        }
        __syncthreads();

        float accS[8];
        #pragma unroll
        for (int i = 0; i < 8; i++) accS[i] = 0.f;

        for (int d0 = 0; d0 < 64; d0 += 4) {
            float4 kv = *(const float4*)&Ks[col * KPAD + d0];
            #pragma unroll
            for (int i = 0; i < 8; i++) {
                float4 qv = *(const float4*)&Qs[(rgrp + 4 * i) * 64 + d0];
                accS[i] = fmaf(qv.x, kv.x, accS[i]);
                accS[i] = fmaf(qv.y, kv.y, accS[i]);
                accS[i] = fmaf(qv.z, kv.z, accS[i]);
                accS[i] = fmaf(qv.w, kv.w, accS[i]);
            }
        }
        #pragma unroll
        for (int i = 0; i < 8; i++)
            Ssm[(rgrp + 4 * i) * 1024 + kt * 64 + col] = accS[i];
    }
    __syncthreads();

    const int warp = tid >> 5, lane = tid & 31;
    for (int rr = warp * 4; rr < warp * 4 + 4; rr++) {
        const int grow = r0 + rr;
        float* Srow = Ssm + rr * 1024;
        const float* mrow = mask_s + (size_t)grow * 1024;
        float mx = -1e30f;
        for (int c = lane; c < 1024; c += 32) {
            float s = Srow[c] * 0.125f + mrow[c];
            Srow[c] = s;
            mx = fmaxf(mx, s);
        }
        #pragma unroll
        for (int o = 16; o > 0; o >>= 1) mx = fmaxf(mx, __shfl_xor_sync(0xffffffffu, mx, o));
        float sum = 0.f;
        for (int c = lane; c < 1024; c += 32) {
            float e = __expf(Srow[c] - mx);
            Srow[c] = e;
            sum += e;
        }
        #pragma unroll
        for (int o = 16; o > 0; o >>= 1) sum += __shfl_xor_sync(0xffffffffu, sum, o);
        float inv = 1.f / sum;
        float* arow = attn_s + ((size_t)(b * 8 + j) * 1024 + grow) * 1024;
        for (int c = lane; c < 1024; c += 32) {
            float p = Srow[c] * inv;
            Srow[c] = p;
            arow[c] = p;
        }
    }
    __syncthreads();

    float accO[8];
    #pragma unroll
    for (int i = 0; i < 8; i++) accO[i] = 0.f;

    for (int kt = 0; kt < 16; kt++) {
        __syncthreads();
        for (int i = tid; i < 1024; i += 256) {
            float4 v = ((const float4*)(Vb + (size_t)kt * 4096))[i];
            int rr = i >> 4, cc = (i & 15) << 2;
            *(float4*)&Vs[rr * KPAD + cc] = v;
        }
        __syncthreads();

        for (int k0 = 0; k0 < 64; k0 += 4) {
            float v0 = Vs[(k0 + 0) * KPAD + col];
            float v1 = Vs[(k0 + 1) * KPAD + col];
            float v2 = Vs[(k0 + 2) * KPAD + col];
            float v3 = Vs[(k0 + 3) * KPAD + col];
            #pragma unroll
            for (int i = 0; i < 8; i++) {
                float4 p = *(const float4*)&Ssm[(rgrp + 4 * i) * 1024 + kt * 64 + k0];
                accO[i] = fmaf(p.x, v0, accO[i]);
                accO[i] = fmaf(p.y, v1, accO[i]);
                accO[i] = fmaf(p.z, v2, accO[i]);
                accO[i] = fmaf(p.w, v3, accO[i]);
            }
        }
    }
    #pragma unroll
    for (int i = 0; i < 8; i++) {
        int row = rgrp + 4 * i;
        out_cat[((size_t)b * 1024 + r0 + row) * 1024 + j * 64 + col] = accO[i];
    }
}

// ---------------------------------------------------------------------------
// Odd-head "feature" attention (unchanged).
// ---------------------------------------------------------------------------
#define SMEM_FEAT ((2*64*64 + 64*65) * 4)
__global__ __launch_bounds__(256) void attn_feat_k(
    const float* __restrict__ Qh, const float* __restrict__ Kh,
    const float* __restrict__ Vh, const float* __restrict__ mask_f,
    float* __restrict__ attn_f, float* __restrict__ out_cat)
{
    extern __shared__ float sm[];
    float* Qt  = sm;
    float* Kt  = Qt + 4096;
    float* Asm = Kt + 4096;

    const int jp = blockIdx.x, b = blockIdx.y;
    const int h = 2 * jp + 1;
    const int tid = threadIdx.x;
    const size_t headoff = (size_t)(b * 16 + h) * 1024 * 64;
    const float* Qb = Qh + headoff;
    const float* Kb = Kh + headoff;
    const float* Vb = Vh + headoff;

    const int m  = tid & 63;
    const int g4 = tid >> 6;

    float acc[16];
    #pragma unroll
    for (int i = 0; i < 16; i++) acc[i] = 0.f;

    for (int lt = 0; lt < 16; lt++) {
        __syncthreads();
        for (int i = tid; i < 1024; i += 256) {
            ((float4*)Qt)[i] = ((const float4*)(Qb + (size_t)lt * 4096))[i];
            ((float4*)Kt)[i] = ((const float4*)(Kb + (size_t)lt * 4096))[i];
        }
        __syncthreads();
        for (int ll = 0; ll < 64; ll++) {
            float kk = Kt[ll * 64 + m];
            #pragma unroll
            for (int i = 0; i < 16; i++)
                acc[i] = fmaf(Qt[ll * 64 + g4 + 4 * i], kk, acc[i]);
        }
    }
    __syncthreads();
    #pragma unroll
    for (int i = 0; i < 16; i++) {
        int n = g4 + 4 * i;
        Asm[n * 65 + m] = acc[i] * 0.125f + mask_f[n * 64 + m];
    }
    __syncthreads();

    const int warp = tid >> 5, lane = tid & 31;
    for (int n = warp * 8; n < warp * 8 + 8; n++) {
        float* row = Asm + n * 65;
        float a0 = row[lane], a1 = row[lane + 32];
        float mx = fmaxf(a0, a1);
        #pragma unroll
        for (int o = 16; o > 0; o >>= 1) mx = fmaxf(mx, __shfl_xor_sync(0xffffffffu, mx, o));
        float e0 = __expf(a0 - mx), e1 = __expf(a1 - mx);
        float s = e0 + e1;
        #pragma unroll
        for (int o = 16; o > 0; o >>= 1) s += __shfl_xor_sync(0xffffffffu, s, o);
        float inv = 1.f / s;
        e0 *= inv; e1 *= inv;
        row[lane] = e0; row[lane + 32] = e1;
        float* grow = attn_f + ((size_t)(b * 8 + jp) * 64 + n) * 64;
        grow[lane] = e0; grow[lane + 32] = e1;
    }
    __syncthreads();

    float* Vt = Qt;
    const int n2 = m;
    for (int lt = 0; lt < 16; lt++) {
        __syncthreads();
        for (int i = tid; i < 1024; i += 256)
            ((float4*)Vt)[i] = ((const float4*)(Vb + (size_t)lt * 4096))[i];
        __syncthreads();

        float accO[16];
        #pragma unroll
        for (int i = 0; i < 16; i++) accO[i] = 0.f;
        for (int mm = 0; mm < 64; mm++) {
            float aa = Asm[n2 * 65 + mm];
            #pragma unroll
            for (int i = 0; i < 16; i++)
                accO[i] = fmaf(Vt[(g4 + 4 * i) * 64 + mm], aa, accO[i]);
        }
        #pragma unroll
        for (int i = 0; i < 16; i++) {
            int ll = g4 + 4 * i;
            out_cat[((size_t)b * 1024 + lt * 64 + ll) * 1024 + (8 + jp) * 64 + n2] = accO[i];
        }
    }
}

// ---------------------------------------------------------------------------
extern "C" void kernel_launch(void* const* d_in, const int* in_sizes, int n_in,
                              void* d_out, int out_size)
{
    const float* q      = (const float*)d_in[0];
    const float* k      = (const float*)d_in[1];
    const float* v      = (const float*)d_in[2];
    const float* mask_s = (const float*)d_in[3];
    const float* mask_f = (const float*)d_in[4];
    const float* Wq     = (const float*)d_in[5];
    const float* Wk     = (const float*)d_in[6];
    const float* Wv     = (const float*)d_in[7];
    const float* Wo     = (const float*)d_in[8];

    float* out    = (float*)d_out;
    float* attn_s = out + OUT_ELEMS;
    float* attn_f = attn_s + ATTNS_ELEMS;

    float *qh, *kh, *vh, *cat;
    __nv_bfloat16 *ahi, *alo, *whi, *wlo;
    cudaGetSymbolAddress((void**)&qh,  g_qh);
    cudaGetSymbolAddress((void**)&kh,  g_kh);
    cudaGetSymbolAddress((void**)&vh,  g_vh);
    cudaGetSymbolAddress((void**)&cat, g_cat);
    cudaGetSymbolAddress((void**)&ahi, g_ahi);
    cudaGetSymbolAddress((void**)&alo, g_alo);
    cudaGetSymbolAddress((void**)&whi, g_whi);
    cudaGetSymbolAddress((void**)&wlo, g_wlo);

    cudaFuncSetAttribute(attn_even_k, cudaFuncAttributeMaxDynamicSharedMemorySize, SMEM_EVEN);
    cudaFuncSetAttribute(attn_feat_k, cudaFuncAttributeMaxDynamicSharedMemorySize, SMEM_FEAT);

    const int M = Bn * Ln;                    // 16384
    dim3 ggrid(DIMn / 128, M / 128);          // (8, 128)
    dim3 sgrid(OUT_ELEMS / (256 * 4));        // activation split
    dim3 wgrid(32, 32), wblk(32, 8);          // weight split/transpose

    // Q projection
    split_a_k<<<sgrid, 256>>>(q, ahi, alo);
    split_w_k<<<wgrid, wblk>>>(Wq, whi, wlo);
    gemm_bf16s_k<1><<<ggrid, 256>>>(ahi, alo, whi, wlo, qh, M, DIMn, DIMn);
    // K projection
    split_a_k<<<sgrid, 256>>>(k, ahi, alo);
    split_w_k<<<wgrid, wblk>>>(Wk, whi, wlo);
    gemm_bf16s_k<1><<<ggrid, 256>>>(ahi, alo, whi, wlo, kh, M, DIMn, DIMn);
    // V projection
    split_a_k<<<sgrid, 256>>>(v, ahi, alo);
    split_w_k<<<wgrid, wblk>>>(Wv, whi, wlo);
    gemm_bf16s_k<1><<<ggrid, 256>>>(ahi, alo, whi, wlo, vh, M, DIMn, DIMn);

    // Attention
    attn_even_k<<<dim3(32, 8, 16), 256, SMEM_EVEN>>>(qh, kh, vh, mask_s, attn_s, cat);
    attn_feat_k<<<dim3(8, 16), 256, SMEM_FEAT>>>(qh, kh, vh, mask_f, attn_f, cat);

    // Output projection
    split_a_k<<<sgrid, 256>>>(cat, ahi, alo);
    split_w_k<<<wgrid, wblk>>>(Wo, whi, wlo);
    gemm_bf16s_k<0><<<ggrid, 256>>>(ahi, alo, whi, wlo, out, M, DIMn, DIMn);
}

// round 5
// speedup vs baseline: 1.8318x; 1.2639x over previous
#include <cuda_runtime.h>
#include <cuda_bf16.h>
#include <cstdint>
#include <cstddef>

// Problem constants
#define Bn   16
#define Ln   1024
#define DIMn 1024
#define NH   16
#define DK   64

#define OUT_ELEMS    (16*1024*1024)
#define ATTNS_ELEMS  (16*8*1024*1024)
#define ATTNF_ELEMS  (16*8*64*64)

// fp32 scratch (head-major Qh/Kh/Vh, concat buffer)
__device__ float g_qh[OUT_ELEMS];
__device__ float g_kh[OUT_ELEMS];
__device__ float g_vh[OUT_ELEMS];
__device__ float g_cat[OUT_ELEMS];
// bf16 split scratch (reused across the 4 GEMMs)
__device__ __nv_bfloat16 g_ahi[OUT_ELEMS];
__device__ __nv_bfloat16 g_alo[OUT_ELEMS];
__device__ __nv_bfloat16 g_whi[DIMn*DIMn];
__device__ __nv_bfloat16 g_wlo[DIMn*DIMn];

// ===========================================================================
// Split kernels: fp32 -> bf16 hi + bf16 lo (Dekker 2-term)
// ===========================================================================
__global__ __launch_bounds__(256) void split_a_k(
    const float* __restrict__ X, __nv_bfloat16* __restrict__ hi,
    __nv_bfloat16* __restrict__ lo)
{
    int i = (blockIdx.x * 256 + threadIdx.x) * 4;
    float4 v = *(const float4*)(X + i);
    float x[4] = {v.x, v.y, v.z, v.w};
    __nv_bfloat16 h[4], l[4];
    #pragma unroll
    for (int j = 0; j < 4; j++) {
        h[j] = __float2bfloat16(x[j]);
        l[j] = __float2bfloat16(x[j] - __bfloat162float(h[j]));
    }
    __nv_bfloat162* hp = (__nv_bfloat162*)(hi + i);
    __nv_bfloat162* lp = (__nv_bfloat162*)(lo + i);
    hp[0] = __nv_bfloat162{h[0], h[1]}; hp[1] = __nv_bfloat162{h[2], h[3]};
    lp[0] = __nv_bfloat162{l[0], l[1]}; lp[1] = __nv_bfloat162{l[2], l[3]};
}

// Weight split + transpose: W[K][N] fp32 -> Wt_hi/lo[N][K] bf16
__global__ __launch_bounds__(256) void split_w_k(
    const float* __restrict__ W, __nv_bfloat16* __restrict__ hi,
    __nv_bfloat16* __restrict__ lo)
{
    __shared__ float t[32][33];
    const int tx = threadIdx.x, ty = threadIdx.y;
    const int n0 = blockIdx.x * 32, k0 = blockIdx.y * 32;
    #pragma unroll
    for (int j = 0; j < 32; j += 8)
        t[ty + j][tx] = W[(size_t)(k0 + ty + j) * DIMn + n0 + tx];
    __syncthreads();
    #pragma unroll
    for (int j = 0; j < 32; j += 8) {
        int n = n0 + ty + j, kk = k0 + tx;
        float x = t[tx][ty + j];
        __nv_bfloat16 h = __float2bfloat16(x);
        __nv_bfloat16 l = __float2bfloat16(x - __bfloat162float(h));
        hi[(size_t)n * DIMn + kk] = h;
        lo[(size_t)n * DIMn + kk] = l;
    }
}

// ===========================================================================
// Split-bf16 mma.sync GEMM with ldmatrix: C(fp32) = A @ B.
// A[M][K] hi/lo row-major; Bt[N][K] hi/lo (k-contiguous).
// CTA 128x128, BK=32, 8 warps (2x4), warp 64x32, m16n8k16:
//   acc += Ah*Bh + Ah*Bl + Al*Bh.
// Smem rows padded to 80B -> ldmatrix conflict-free. 2-stage cp.async, occ 2.
// MODE 0: row-major C; MODE 1: head-major C.
// ===========================================================================
#define RS      40                  // bf16 per smem row (80 B)
#define TILB    (128*RS*2)          // 10240 B per tile
#define STAGEB  (4*TILB)            // Ahi,Alo,Bhi,Blo
#define GSMEM   (2*STAGEB)          // 81920 B

#define CP_ASYNC16(dst, src) \
    asm volatile("cp.async.cg.shared.global [%0], [%1], 16;\n" :: "r"(dst), "l"(src))
#define CP_COMMIT() asm volatile("cp.async.commit_group;\n" ::: "memory")
#define CP_WAIT(n)  asm volatile("cp.async.wait_group %0;\n" :: "n"(n) : "memory")

#define LDSM_X4(r0, r1, r2, r3, addr) \
    asm volatile("ldmatrix.sync.aligned.m8n8.x4.shared.b16 {%0,%1,%2,%3}, [%4];" \
                 : "=r"(r0), "=r"(r1), "=r"(r2), "=r"(r3) : "r"(addr))

__device__ __forceinline__ void mma_bf16(float c[4], const uint32_t a[4], const uint32_t b[2]) {
    asm volatile(
        "mma.sync.aligned.m16n8k16.row.col.f32.bf16.bf16.f32 "
        "{%0,%1,%2,%3}, {%4,%5,%6,%7}, {%8,%9}, {%0,%1,%2,%3};\n"
        : "+f"(c[0]), "+f"(c[1]), "+f"(c[2]), "+f"(c[3])
        : "r"(a[0]), "r"(a[1]), "r"(a[2]), "r"(a[3]), "r"(b[0]), "r"(b[1]));
}

template<int MODE>
__global__ __launch_bounds__(256, 2) void gemm_lm_k(
    const __nv_bfloat16* __restrict__ Ahi, const __nv_bfloat16* __restrict__ Alo,
    const __nv_bfloat16* __restrict__ Bhi, const __nv_bfloat16* __restrict__ Blo,
    float* __restrict__ C)
{
    extern __shared__ char smem[];
    uint32_t sb;
    asm("{ .reg .u64 u; cvta.to.shared.u64 u, %1; cvt.u32.u64 %0, u; }" : "=r"(sb) : "l"(smem));

    const int tid  = threadIdx.x;
    const int lane = tid & 31;
    const int warp = tid >> 5;
    const int wm   = warp >> 2;    // 0..1
    const int wn   = warp & 3;     // 0..3
    const int g    = lane >> 2;    // 0..7
    const int t4   = lane & 3;     // 0..3

    const int row0 = blockIdx.y * 128;
    const int col0 = blockIdx.x * 128;

    // ldmatrix per-lane offsets (bytes within a tile)
    const int sub = lane >> 3, r8 = lane & 7;
    const uint32_t loffA = (uint32_t)((r8 + (sub & 1) * 8) * 80 + (sub >> 1) * 16);
    const uint32_t loffB = (uint32_t)((r8 + (sub >> 1) * 8) * 80 + (sub & 1) * 16);

    // cp.async mapping: per tile, 512 x 16B chunks; thread does idx tid, tid+256
    const int r_0 = tid >> 2, ch0 = tid & 3;
    const int r_1 = (tid + 256) >> 2, ch1 = ch0;

    auto prefetch = [&](int c, int st) {
        const int kc = c * 32;
        uint32_t s0 = sb + (uint32_t)st * STAGEB;
        {
            uint32_t d = s0 + (uint32_t)(r_0 * 80 + ch0 * 16);
            size_t ga = ((size_t)(row0 + r_0) * 1024 + kc + ch0 * 8) * 2;
            size_t gb = ((size_t)(col0 + r_0) * 1024 + kc + ch0 * 8) * 2;
            CP_ASYNC16(d,            (const char*)Ahi + ga);
            CP_ASYNC16(d + TILB,     (const char*)Alo + ga);
            CP_ASYNC16(d + 2*TILB,   (const char*)Bhi + gb);
            CP_ASYNC16(d + 3*TILB,   (const char*)Blo + gb);
        }
        {
            uint32_t d = s0 + (uint32_t)(r_1 * 80 + ch1 * 16);
            size_t ga = ((size_t)(row0 + r_1) * 1024 + kc + ch1 * 8) * 2;
            size_t gb = ((size_t)(col0 + r_1) * 1024 + kc + ch1 * 8) * 2;
            CP_ASYNC16(d,            (const char*)Ahi + ga);
            CP_ASYNC16(d + TILB,     (const char*)Alo + ga);
            CP_ASYNC16(d + 2*TILB,   (const char*)Bhi + gb);
            CP_ASYNC16(d + 3*TILB,   (const char*)Blo + gb);
        }
    };

    float acc[4][4][4];
    #pragma unroll
    for (int mt = 0; mt < 4; mt++)
        #pragma unroll
        for (int nt = 0; nt < 4; nt++)
            #pragma unroll
            for (int i = 0; i < 4; i++) acc[mt][nt][i] = 0.f;

    prefetch(0, 0); CP_COMMIT();
    prefetch(1, 1); CP_COMMIT();

    const int nk = 32;   // K=1024 / BK=32
    for (int c = 0; c < nk; c++) {
        const int st = c & 1;
        if (c + 1 < nk) { CP_WAIT(1); } else { CP_WAIT(0); }
        __syncthreads();

        const uint32_t s0 = sb + (uint32_t)st * STAGEB;
        const uint32_t aB = s0 + (uint32_t)(wm * 64) * 80;
        const uint32_t bB = s0 + 2 * TILB + (uint32_t)(wn * 32) * 80;

        #pragma unroll
        for (int ks = 0; ks < 2; ks++) {
            const uint32_t kb = ks * 32;   // 16 bf16 = 32 bytes
            uint32_t bh[4][2], bl[4][2];
            #pragma unroll
            for (int p = 0; p < 2; p++) {
                uint32_t base = bB + (uint32_t)(p * 16) * 80 + kb;
                LDSM_X4(bh[2*p][0], bh[2*p][1], bh[2*p+1][0], bh[2*p+1][1], base + loffB);
                LDSM_X4(bl[2*p][0], bl[2*p][1], bl[2*p+1][0], bl[2*p+1][1], base + TILB + loffB);
            }
            #pragma unroll
            for (int mt = 0; mt < 4; mt++) {
                uint32_t abase = aB + (uint32_t)(mt * 16) * 80 + kb;
                uint32_t ah[4], al[4];
                LDSM_X4(ah[0], ah[1], ah[2], ah[3], abase + loffA);
                LDSM_X4(al[0], al[1], al[2], al[3], abase + TILB + loffA);
                #pragma unroll
                for (int nt = 0; nt < 4; nt++) {
                    mma_bf16(acc[mt][nt], ah, bh[nt]);
                    mma_bf16(acc[mt][nt], ah, bl[nt]);
                    mma_bf16(acc[mt][nt], al, bh[nt]);
                }
            }
        }
        __syncthreads();
        if (c + 2 < nk) { prefetch(c + 2, st); CP_COMMIT(); }
    }

    // Epilogue
    #pragma unroll
    for (int mt = 0; mt < 4; mt++) {
        #pragma unroll
        for (int nt = 0; nt < 4; nt++) {
            int r = row0 + wm * 64 + mt * 16 + g;
            int c = col0 + wn * 32 + nt * 8 + 2 * t4;
            float2 v0 = make_float2(acc[mt][nt][0], acc[mt][nt][1]);
            float2 v1 = make_float2(acc[mt][nt][2], acc[mt][nt][3]);
            if (MODE == 0) {
                *(float2*)(C + (size_t)r * 1024 + c)       = v0;
                *(float2*)(C + (size_t)(r + 8) * 1024 + c) = v1;
            } else {
                int b_ = r >> 10, l0 = r & 1023;
                int h_ = c >> 6,  d_ = c & 63;
                size_t base = ((size_t)(b_ * 16 + h_) * 1024) * 64 + d_;
                *(float2*)(C + base + (size_t)l0 * 64)       = v0;
                *(float2*)(C + base + (size_t)(l0 + 8) * 64) = v1;
            }
        }
    }
}

// ---------------------------------------------------------------------------
// Even-head attention, 512 threads (16 warps), same smem layout as R1.
// Block = (qtile 32 rows, head-slot j (orig head 2j), b).
// ---------------------------------------------------------------------------
#define KPAD 68
#define SMEM_EVEN ((32*1024 + 32*64 + 2*64*KPAD) * 4)
__global__ __launch_bounds__(512) void attn_even_k(
    const float* __restrict__ Qh, const float* __restrict__ Kh,
    const float* __restrict__ Vh, const float* __restrict__ mask_s,
    float* __restrict__ attn_s, float* __restrict__ out_cat)
{
    extern __shared__ float sm[];
    float* Ssm = sm;
    float* Qs  = Ssm + 32 * 1024;
    float* Ks  = Qs + 32 * 64;
    float* Vs  = Ks + 64 * KPAD;

    const int qt = blockIdx.x, j = blockIdx.y, b = blockIdx.z;
    const int h = 2 * j;
    const int tid = threadIdx.x;
    const size_t headoff = (size_t)(b * 16 + h) * 1024 * 64;
    const float* Qb = Qh + headoff;
    const float* Kb = Kh + headoff;
    const float* Vb = Vh + headoff;
    const int r0 = qt * 32;

    // Load Q tile (32x64 = 512 float4)
    ((float4*)Qs)[tid] = ((const float4*)(Qb + (size_t)r0 * 64))[tid];

    const int col  = tid & 63;   // K-seq index within tile / d-index
    const int rgrp = tid >> 6;   // 0..7

    // ---- S = Q Kᵀ over 16 K tiles ----
    for (int kt = 0; kt < 16; kt++) {
        __syncthreads();
        for (int i = tid; i < 1024; i += 512) {
            float4 v = ((const float4*)(Kb + (size_t)kt * 4096))[i];
            int rr = i >> 4, cc = (i & 15) << 2;
            *(float4*)&Ks[rr * KPAD + cc] = v;
        }
        __syncthreads();

        float accS[4];
        #pragma unroll
        for (int i = 0; i < 4; i++) accS[i] = 0.f;

        for (int d0 = 0; d0 < 64; d0 += 4) {
            float4 kv = *(const float4*)&Ks[col * KPAD + d0];
            #pragma unroll
            for (int i = 0; i < 4; i++) {
                float4 qv = *(const float4*)&Qs[(rgrp + 8 * i) * 64 + d0];
                accS[i] = fmaf(qv.x, kv.x, accS[i]);
                accS[i] = fmaf(qv.y, kv.y, accS[i]);
                accS[i] = fmaf(qv.z, kv.z, accS[i]);
                accS[i] = fmaf(qv.w, kv.w, accS[i]);
            }
        }
        #pragma unroll
        for (int i = 0; i < 4; i++)
            Ssm[(rgrp + 8 * i) * 1024 + kt * 64 + col] = accS[i];
    }
    __syncthreads();

    // ---- softmax: 16 warps x 2 rows ----
    const int warp = tid >> 5, lane = tid & 31;
    for (int rr = warp * 2; rr < warp * 2 + 2; rr++) {
        const int grow = r0 + rr;
        float* Srow = Ssm + rr * 1024;
        const float* mrow = mask_s + (size_t)grow * 1024;
        float mx = -1e30f;
        for (int c = lane; c < 1024; c += 32) {
            float s = Srow[c] * 0.125f + mrow[c];
            Srow[c] = s;
            mx = fmaxf(mx, s);
        }
        #pragma unroll
        for (int o = 16; o > 0; o >>= 1) mx = fmaxf(mx, __shfl_xor_sync(0xffffffffu, mx, o));
        float sum = 0.f;
        for (int c = lane; c < 1024; c += 32) {
            float e = __expf(Srow[c] - mx);
            Srow[c] = e;
            sum += e;
        }
        #pragma unroll
        for (int o = 16; o > 0; o >>= 1) sum += __shfl_xor_sync(0xffffffffu, sum, o);
        float inv = 1.f / sum;
        float* arow = attn_s + ((size_t)(b * 8 + j) * 1024 + grow) * 1024;
        for (int c = lane; c < 1024; c += 32) {
            float p = Srow[c] * inv;
            Srow[c] = p;
            arow[c] = p;
        }
    }
    __syncthreads();

    // ---- O = P V over 16 V tiles ----
    float accO[4];
    #pragma unroll
    for (int i = 0; i < 4; i++) accO[i] = 0.f;

    for (int kt = 0; kt < 16; kt++) {
        __syncthreads();
        for (int i = tid; i < 1024; i += 512) {
            float4 v = ((const float4*)(Vb + (size_t)kt * 4096))[i];
            int rr = i >> 4, cc = (i & 15) << 2;
            *(float4*)&Vs[rr * KPAD + cc] = v;
        }
        __syncthreads();

        for (int k0 = 0; k0 < 64; k0 += 4) {
            float v0 = Vs[(k0 + 0) * KPAD + col];
            float v1 = Vs[(k0 + 1) * KPAD + col];
            float v2 = Vs[(k0 + 2) * KPAD + col];
            float v3 = Vs[(k0 + 3) * KPAD + col];
            #pragma unroll
            for (int i = 0; i < 4; i++) {
                float4 p = *(const float4*)&Ssm[(rgrp + 8 * i) * 1024 + kt * 64 + k0];
                accO[i] = fmaf(p.x, v0, accO[i]);
                accO[i] = fmaf(p.y, v1, accO[i]);
                accO[i] = fmaf(p.z, v2, accO[i]);
                accO[i] = fmaf(p.w, v3, accO[i]);
            }
        }
    }
    #pragma unroll
    for (int i = 0; i < 4; i++) {
        int row = rgrp + 8 * i;
        out_cat[((size_t)b * 1024 + r0 + row) * 1024 + j * 64 + col] = accO[i];
    }
}

// ---------------------------------------------------------------------------
// Odd-head "feature" attention (unchanged).
// ---------------------------------------------------------------------------
#define SMEM_FEAT ((2*64*64 + 64*65) * 4)
__global__ __launch_bounds__(256) void attn_feat_k(
    const float* __restrict__ Qh, const float* __restrict__ Kh,
    const float* __restrict__ Vh, const float* __restrict__ mask_f,
    float* __restrict__ attn_f, float* __restrict__ out_cat)
{
    extern __shared__ float sm[];
    float* Qt  = sm;
    float* Kt  = Qt + 4096;
    float* Asm = Kt + 4096;

    const int jp = blockIdx.x, b = blockIdx.y;
    const int h = 2 * jp + 1;
    const int tid = threadIdx.x;
    const size_t headoff = (size_t)(b * 16 + h) * 1024 * 64;
    const float* Qb = Qh + headoff;
    const float* Kb = Kh + headoff;
    const float* Vb = Vh + headoff;

    const int m  = tid & 63;
    const int g4 = tid >> 6;

    float acc[16];
    #pragma unroll
    for (int i = 0; i < 16; i++) acc[i] = 0.f;

    for (int lt = 0; lt < 16; lt++) {
        __syncthreads();
        for (int i = tid; i < 1024; i += 256) {
            ((float4*)Qt)[i] = ((const float4*)(Qb + (size_t)lt * 4096))[i];
            ((float4*)Kt)[i] = ((const float4*)(Kb + (size_t)lt * 4096))[i];
        }
        __syncthreads();
        for (int ll = 0; ll < 64; ll++) {
            float kk = Kt[ll * 64 + m];
            #pragma unroll
            for (int i = 0; i < 16; i++)
                acc[i] = fmaf(Qt[ll * 64 + g4 + 4 * i], kk, acc[i]);
        }
    }
    __syncthreads();
    #pragma unroll
    for (int i = 0; i < 16; i++) {
        int n = g4 + 4 * i;
        Asm[n * 65 + m] = acc[i] * 0.125f + mask_f[n * 64 + m];
    }
    __syncthreads();

    const int warp = tid >> 5, lane = tid & 31;
    for (int n = warp * 8; n < warp * 8 + 8; n++) {
        float* row = Asm + n * 65;
        float a0 = row[lane], a1 = row[lane + 32];
        float mx = fmaxf(a0, a1);
        #pragma unroll
        for (int o = 16; o > 0; o >>= 1) mx = fmaxf(mx, __shfl_xor_sync(0xffffffffu, mx, o));
        float e0 = __expf(a0 - mx), e1 = __expf(a1 - mx);
        float s = e0 + e1;
        #pragma unroll
        for (int o = 16; o > 0; o >>= 1) s += __shfl_xor_sync(0xffffffffu, s, o);
        float inv = 1.f / s;
        e0 *= inv; e1 *= inv;
        row[lane] = e0; row[lane + 32] = e1;
        float* grow = attn_f + ((size_t)(b * 8 + jp) * 64 + n) * 64;
        grow[lane] = e0; grow[lane + 32] = e1;
    }
    __syncthreads();

    float* Vt = Qt;
    const int n2 = m;
    for (int lt = 0; lt < 16; lt++) {
        __syncthreads();
        for (int i = tid; i < 1024; i += 256)
            ((float4*)Vt)[i] = ((const float4*)(Vb + (size_t)lt * 4096))[i];
        __syncthreads();

        float accO[16];
        #pragma unroll
        for (int i = 0; i < 16; i++) accO[i] = 0.f;
        for (int mm = 0; mm < 64; mm++) {
            float aa = Asm[n2 * 65 + mm];
            #pragma unroll
            for (int i = 0; i < 16; i++)
                accO[i] = fmaf(Vt[(g4 + 4 * i) * 64 + mm], aa, accO[i]);
        }
        #pragma unroll
        for (int i = 0; i < 16; i++) {
            int ll = g4 + 4 * i;
            out_cat[((size_t)b * 1024 + lt * 64 + ll) * 1024 + (8 + jp) * 64 + n2] = accO[i];
        }
    }
}

// ---------------------------------------------------------------------------
extern "C" void kernel_launch(void* const* d_in, const int* in_sizes, int n_in,
                              void* d_out, int out_size)
{
    const float* q      = (const float*)d_in[0];
    const float* k      = (const float*)d_in[1];
    const float* v      = (const float*)d_in[2];
    const float* mask_s = (const float*)d_in[3];
    const float* mask_f = (const float*)d_in[4];
    const float* Wq     = (const float*)d_in[5];
    const float* Wk     = (const float*)d_in[6];
    const float* Wv     = (const float*)d_in[7];
    const float* Wo     = (const float*)d_in[8];

    float* out    = (float*)d_out;
    float* attn_s = out + OUT_ELEMS;
    float* attn_f = attn_s + ATTNS_ELEMS;

    float *qh, *kh, *vh, *cat;
    __nv_bfloat16 *ahi, *alo, *whi, *wlo;
    cudaGetSymbolAddress((void**)&qh,  g_qh);
    cudaGetSymbolAddress((void**)&kh,  g_kh);
    cudaGetSymbolAddress((void**)&vh,  g_vh);
    cudaGetSymbolAddress((void**)&cat, g_cat);
    cudaGetSymbolAddress((void**)&ahi, g_ahi);
    cudaGetSymbolAddress((void**)&alo, g_alo);
    cudaGetSymbolAddress((void**)&whi, g_whi);
    cudaGetSymbolAddress((void**)&wlo, g_wlo);

    cudaFuncSetAttribute(attn_even_k, cudaFuncAttributeMaxDynamicSharedMemorySize, SMEM_EVEN);
    cudaFuncSetAttribute(attn_feat_k, cudaFuncAttributeMaxDynamicSharedMemorySize, SMEM_FEAT);
    cudaFuncSetAttribute(gemm_lm_k<0>, cudaFuncAttributeMaxDynamicSharedMemorySize, GSMEM);
    cudaFuncSetAttribute(gemm_lm_k<1>, cudaFuncAttributeMaxDynamicSharedMemorySize, GSMEM);

    dim3 ggrid(DIMn / 128, (Bn * Ln) / 128);  // (8, 128)
    dim3 sgrid(OUT_ELEMS / (256 * 4));        // activation split
    dim3 wgrid(32, 32), wblk(32, 8);          // weight split/transpose

    // Q projection
    split_a_k<<<sgrid, 256>>>(q, ahi, alo);
    split_w_k<<<wgrid, wblk>>>(Wq, whi, wlo);
    gemm_lm_k<1><<<ggrid, 256, GSMEM>>>(ahi, alo, whi, wlo, qh);
    // K projection
    split_a_k<<<sgrid, 256>>>(k, ahi, alo);
    split_w_k<<<wgrid, wblk>>>(Wk, whi, wlo);
    gemm_lm_k<1><<<ggrid, 256, GSMEM>>>(ahi, alo, whi, wlo, kh);
    // V projection
    split_a_k<<<sgrid, 256>>>(v, ahi, alo);
    split_w_k<<<wgrid, wblk>>>(Wv, whi, wlo);
    gemm_lm_k<1><<<ggrid, 256, GSMEM>>>(ahi, alo, whi, wlo, vh);

    // Attention
    attn_even_k<<<dim3(32, 8, 16), 512, SMEM_EVEN>>>(qh, kh, vh, mask_s, attn_s, cat);
    attn_feat_k<<<dim3(8, 16), 256, SMEM_FEAT>>>(qh, kh, vh, mask_f, attn_f, cat);

    // Output projection
    split_a_k<<<sgrid, 256>>>(cat, ahi, alo);
    split_w_k<<<wgrid, wblk>>>(Wo, whi, wlo);
    gemm_lm_k<0><<<ggrid, 256, GSMEM>>>(ahi, alo, whi, wlo, out);
}

// round 6
// speedup vs baseline: 3.0863x; 1.6848x over previous
#include <cuda_runtime.h>
#include <cuda_bf16.h>
#include <cstdint>
#include <cstddef>

// Problem constants
#define Bn   16
#define Ln   1024
#define DIMn 1024
#define NH   16
#define DK   64

#define OUT_ELEMS    (16*1024*1024)
#define ATTNS_ELEMS  (16*8*1024*1024)
#define ATTNF_ELEMS  (16*8*64*64)

// fp32 scratch (head-major Qh/Kh/Vh, concat buffer)
__device__ float g_qh[OUT_ELEMS];
__device__ float g_kh[OUT_ELEMS];
__device__ float g_vh[OUT_ELEMS];
__device__ float g_cat[OUT_ELEMS];
// bf16 split scratch (reused across the 4 GEMMs)
__device__ __nv_bfloat16 g_ahi[OUT_ELEMS];
__device__ __nv_bfloat16 g_alo[OUT_ELEMS];
__device__ __nv_bfloat16 g_whi[DIMn*DIMn];
__device__ __nv_bfloat16 g_wlo[DIMn*DIMn];

// ===========================================================================
// Common helpers
// ===========================================================================
#define CP_ASYNC16(dst, src) \
    asm volatile("cp.async.cg.shared.global [%0], [%1], 16;\n" :: "r"(dst), "l"(src))
#define CP_COMMIT() asm volatile("cp.async.commit_group;\n" ::: "memory")
#define CP_WAIT(n)  asm volatile("cp.async.wait_group %0;\n" :: "n"(n) : "memory")

#define LDSM_X4(r0, r1, r2, r3, addr) \
    asm volatile("ldmatrix.sync.aligned.m8n8.x4.shared.b16 {%0,%1,%2,%3}, [%4];" \
                 : "=r"(r0), "=r"(r1), "=r"(r2), "=r"(r3) : "r"(addr))
#define LDSM_X2(r0, r1, addr) \
    asm volatile("ldmatrix.sync.aligned.m8n8.x2.shared.b16 {%0,%1}, [%2];" \
                 : "=r"(r0), "=r"(r1) : "r"(addr))
#define LDSM_X2_T(r0, r1, addr) \
    asm volatile("ldmatrix.sync.aligned.m8n8.x2.trans.shared.b16 {%0,%1}, [%2];" \
                 : "=r"(r0), "=r"(r1) : "r"(addr))

__device__ __forceinline__ void mma_bf16(float c[4], const uint32_t a[4], const uint32_t b[2]) {
    asm volatile(
        "mma.sync.aligned.m16n8k16.row.col.f32.bf16.bf16.f32 "
        "{%0,%1,%2,%3}, {%4,%5,%6,%7}, {%8,%9}, {%0,%1,%2,%3};\n"
        : "+f"(c[0]), "+f"(c[1]), "+f"(c[2]), "+f"(c[3])
        : "r"(a[0]), "r"(a[1]), "r"(a[2]), "r"(a[3]), "r"(b[0]), "r"(b[1]));
}

static __device__ __forceinline__ void split_pack(float x0, float x1,
                                                  uint32_t& hi, uint32_t& lo) {
    __nv_bfloat16 h0 = __float2bfloat16(x0);
    __nv_bfloat16 h1 = __float2bfloat16(x1);
    __nv_bfloat16 l0 = __float2bfloat16(x0 - __bfloat162float(h0));
    __nv_bfloat16 l1 = __float2bfloat16(x1 - __bfloat162float(h1));
    __nv_bfloat162 hp(h0, h1), lp(l0, l1);
    hi = *reinterpret_cast<uint32_t*>(&hp);
    lo = *reinterpret_cast<uint32_t*>(&lp);
}

// ===========================================================================
// Split kernels (fp32 -> bf16 hi/lo), unchanged from R5
// ===========================================================================
__global__ __launch_bounds__(256) void split_a_k(
    const float* __restrict__ X, __nv_bfloat16* __restrict__ hi,
    __nv_bfloat16* __restrict__ lo)
{
    int i = (blockIdx.x * 256 + threadIdx.x) * 4;
    float4 v = *(const float4*)(X + i);
    float x[4] = {v.x, v.y, v.z, v.w};
    __nv_bfloat16 h[4], l[4];
    #pragma unroll
    for (int j = 0; j < 4; j++) {
        h[j] = __float2bfloat16(x[j]);
        l[j] = __float2bfloat16(x[j] - __bfloat162float(h[j]));
    }
    __nv_bfloat162* hp = (__nv_bfloat162*)(hi + i);
    __nv_bfloat162* lp = (__nv_bfloat162*)(lo + i);
    hp[0] = __nv_bfloat162{h[0], h[1]}; hp[1] = __nv_bfloat162{h[2], h[3]};
    lp[0] = __nv_bfloat162{l[0], l[1]}; lp[1] = __nv_bfloat162{l[2], l[3]};
}

__global__ __launch_bounds__(256) void split_w_k(
    const float* __restrict__ W, __nv_bfloat16* __restrict__ hi,
    __nv_bfloat16* __restrict__ lo)
{
    __shared__ float t[32][33];
    const int tx = threadIdx.x, ty = threadIdx.y;
    const int n0 = blockIdx.x * 32, k0 = blockIdx.y * 32;
    #pragma unroll
    for (int j = 0; j < 32; j += 8)
        t[ty + j][tx] = W[(size_t)(k0 + ty + j) * DIMn + n0 + tx];
    __syncthreads();
    #pragma unroll
    for (int j = 0; j < 32; j += 8) {
        int n = n0 + ty + j, kk = k0 + tx;
        float x = t[tx][ty + j];
        __nv_bfloat16 h = __float2bfloat16(x);
        __nv_bfloat16 l = __float2bfloat16(x - __bfloat162float(h));
        hi[(size_t)n * DIMn + kk] = h;
        lo[(size_t)n * DIMn + kk] = l;
    }
}

// ===========================================================================
// Split-bf16 mma.sync GEMM (unchanged from R5, passing)
// ===========================================================================
#define RS      40
#define TILB    (128*RS*2)
#define STAGEB  (4*TILB)
#define GSMEM   (2*STAGEB)

template<int MODE>
__global__ __launch_bounds__(256, 2) void gemm_lm_k(
    const __nv_bfloat16* __restrict__ Ahi, const __nv_bfloat16* __restrict__ Alo,
    const __nv_bfloat16* __restrict__ Bhi, const __nv_bfloat16* __restrict__ Blo,
    float* __restrict__ C)
{
    extern __shared__ char smem[];
    uint32_t sb;
    asm("{ .reg .u64 u; cvta.to.shared.u64 u, %1; cvt.u32.u64 %0, u; }" : "=r"(sb) : "l"(smem));

    const int tid  = threadIdx.x;
    const int lane = tid & 31;
    const int warp = tid >> 5;
    const int wm   = warp >> 2;
    const int wn   = warp & 3;
    const int g    = lane >> 2;
    const int t4   = lane & 3;

    const int row0 = blockIdx.y * 128;
    const int col0 = blockIdx.x * 128;

    const int sub = lane >> 3, r8 = lane & 7;
    const uint32_t loffA = (uint32_t)((r8 + (sub & 1) * 8) * 80 + (sub >> 1) * 16);
    const uint32_t loffB = (uint32_t)((r8 + (sub >> 1) * 8) * 80 + (sub & 1) * 16);

    const int r_0 = tid >> 2, ch0 = tid & 3;
    const int r_1 = (tid + 256) >> 2, ch1 = ch0;

    auto prefetch = [&](int c, int st) {
        const int kc = c * 32;
        uint32_t s0 = sb + (uint32_t)st * STAGEB;
        {
            uint32_t d = s0 + (uint32_t)(r_0 * 80 + ch0 * 16);
            size_t ga = ((size_t)(row0 + r_0) * 1024 + kc + ch0 * 8) * 2;
            size_t gb = ((size_t)(col0 + r_0) * 1024 + kc + ch0 * 8) * 2;
            CP_ASYNC16(d,            (const char*)Ahi + ga);
            CP_ASYNC16(d + TILB,     (const char*)Alo + ga);
            CP_ASYNC16(d + 2*TILB,   (const char*)Bhi + gb);
            CP_ASYNC16(d + 3*TILB,   (const char*)Blo + gb);
        }
        {
            uint32_t d = s0 + (uint32_t)(r_1 * 80 + ch1 * 16);
            size_t ga = ((size_t)(row0 + r_1) * 1024 + kc + ch1 * 8) * 2;
            size_t gb = ((size_t)(col0 + r_1) * 1024 + kc + ch1 * 8) * 2;
            CP_ASYNC16(d,            (const char*)Ahi + ga);
            CP_ASYNC16(d + TILB,     (const char*)Alo + ga);
            CP_ASYNC16(d + 2*TILB,   (const char*)Bhi + gb);
            CP_ASYNC16(d + 3*TILB,   (const char*)Blo + gb);
        }
    };

    float acc[4][4][4];
    #pragma unroll
    for (int mt = 0; mt < 4; mt++)
        #pragma unroll
        for (int nt = 0; nt < 4; nt++)
            #pragma unroll
            for (int i = 0; i < 4; i++) acc[mt][nt][i] = 0.f;

    prefetch(0, 0); CP_COMMIT();
    prefetch(1, 1); CP_COMMIT();

    const int nk = 32;
    for (int c = 0; c < nk; c++) {
        const int st = c & 1;
        if (c + 1 < nk) { CP_WAIT(1); } else { CP_WAIT(0); }
        __syncthreads();

        const uint32_t s0 = sb + (uint32_t)st * STAGEB;
        const uint32_t aB = s0 + (uint32_t)(wm * 64) * 80;
        const uint32_t bB = s0 + 2 * TILB + (uint32_t)(wn * 32) * 80;

        #pragma unroll
        for (int ks = 0; ks < 2; ks++) {
            const uint32_t kb = ks * 32;
            uint32_t bh[4][2], bl[4][2];
            #pragma unroll
            for (int p = 0; p < 2; p++) {
                uint32_t base = bB + (uint32_t)(p * 16) * 80 + kb;
                LDSM_X4(bh[2*p][0], bh[2*p][1], bh[2*p+1][0], bh[2*p+1][1], base + loffB);
                LDSM_X4(bl[2*p][0], bl[2*p][1], bl[2*p+1][0], bl[2*p+1][1], base + TILB + loffB);
            }
            #pragma unroll
            for (int mt = 0; mt < 4; mt++) {
                uint32_t abase = aB + (uint32_t)(mt * 16) * 80 + kb;
                uint32_t ah[4], al[4];
                LDSM_X4(ah[0], ah[1], ah[2], ah[3], abase + loffA);
                LDSM_X4(al[0], al[1], al[2], al[3], abase + TILB + loffA);
                #pragma unroll
                for (int nt = 0; nt < 4; nt++) {
                    mma_bf16(acc[mt][nt], ah, bh[nt]);
                    mma_bf16(acc[mt][nt], ah, bl[nt]);
                    mma_bf16(acc[mt][nt], al, bh[nt]);
                }
            }
        }
        __syncthreads();
        if (c + 2 < nk) { prefetch(c + 2, st); CP_COMMIT(); }
    }

    #pragma unroll
    for (int mt = 0; mt < 4; mt++) {
        #pragma unroll
        for (int nt = 0; nt < 4; nt++) {
            int r = row0 + wm * 64 + mt * 16 + g;
            int c = col0 + wn * 32 + nt * 8 + 2 * t4;
            float2 v0 = make_float2(acc[mt][nt][0], acc[mt][nt][1]);
            float2 v1 = make_float2(acc[mt][nt][2], acc[mt][nt][3]);
            if (MODE == 0) {
                *(float2*)(C + (size_t)r * 1024 + c)       = v0;
                *(float2*)(C + (size_t)(r + 8) * 1024 + c) = v1;
            } else {
                int b_ = r >> 10, l0 = r & 1023;
                int h_ = c >> 6,  d_ = c & 63;
                size_t base = ((size_t)(b_ * 16 + h_) * 1024) * 64 + d_;
                *(float2*)(C + base + (size_t)l0 * 64)       = v0;
                *(float2*)(C + base + (size_t)(l0 + 8) * 64) = v1;
            }
        }
    }
}

// ===========================================================================
// Even-head attention, tensor-core version. 512 threads, block (qt, j, b).
// S = Q K^T and O = P V via split-bf16 m16n8k16 (3 terms each).
// fp32 tiles converted to bf16 hi/lo in-kernel.
// Smem (bytes): Ssm fp32 [32][1032]  = 132096
//               Qs  fp32 [32][68]    = 8704   @132096
//               KV tiles: 2 stages x (hi,lo) x [64][72] bf16 = 36864 @140800
//               P tiles:  2 stages x (hi,lo) x [32][72] bf16 = 18432 @177664
// total 196096
// ===========================================================================
#define SSTR 1032
#define AE_QS   132096
#define AE_KV   140800
#define AE_KVST 18432          // per stage (hi+lo)
#define AE_TL   9216           // one 64x72 bf16 tile
#define AE_P    177664
#define AE_PST  9216           // per stage (hi+lo)
#define AE_PTL  4608           // one 32x72 bf16 tile
#define SMEM_EVEN 196096

__global__ __launch_bounds__(512) void attn_even_k(
    const float* __restrict__ Qh, const float* __restrict__ Kh,
    const float* __restrict__ Vh, const float* __restrict__ mask_s,
    float* __restrict__ attn_s, float* __restrict__ out_cat)
{
    extern __shared__ char smem[];
    float* Ssm = (float*)smem;                 // [32][SSTR]
    float* Qs  = (float*)(smem + AE_QS);       // [32][68]
    uint32_t sb;
    asm("{ .reg .u64 u; cvta.to.shared.u64 u, %1; cvt.u32.u64 %0, u; }" : "=r"(sb) : "l"(smem));

    const int qt = blockIdx.x, j = blockIdx.y, b = blockIdx.z;
    const int h = 2 * j;
    const int tid = threadIdx.x;
    const int warp = tid >> 5, lane = tid & 31;
    const int g = lane >> 2, t4 = lane & 3;
    const int mt = warp >> 3, ntw = warp & 7;
    const int m0 = mt * 16, n0 = ntw * 8;
    const size_t headoff = (size_t)(b * 16 + h) * 1024 * 64;
    const float* Qb = Qh + headoff;
    const float* Kb = Kh + headoff;
    const float* Vb = Vh + headoff;
    const int r0 = qt * 32;

    // tile-load mapping (64 rows x 8 cols of fp32 per thread-slice)
    const int krow = tid >> 3, kcol8 = (tid & 7) * 8;
    // P-convert mapping
    const int pr = tid >> 4, pc = (tid & 15) * 4;

    // ---- load Q tile 32x64 fp32 -> Qs[32][68] ----
    {
        int r = tid >> 4, c = (tid & 15) * 4;
        float4 v = *(const float4*)(Qb + (size_t)(r0 + r) * 64 + c);
        *(float4*)&Qs[r * 68 + c] = v;
    }

    // ---- prefetch K tile 0 into regs ----
    float4 fa, fb;
    fa = *(const float4*)(Kb + (size_t)krow * 64 + kcol8);
    fb = *(const float4*)(Kb + (size_t)krow * 64 + kcol8 + 4);
    __syncthreads();

    // ---- preload Q A-fragments (hi/lo) ----
    uint32_t qhF[4][4], qlF[4][4];
    #pragma unroll
    for (int ks = 0; ks < 4; ks++) {
        int kc = ks * 16 + 2 * t4;
        split_pack(Qs[(m0+g)*68 + kc],     Qs[(m0+g)*68 + kc + 1],     qhF[ks][0], qlF[ks][0]);
        split_pack(Qs[(m0+g+8)*68 + kc],   Qs[(m0+g+8)*68 + kc + 1],   qhF[ks][1], qlF[ks][1]);
        split_pack(Qs[(m0+g)*68 + kc + 8], Qs[(m0+g)*68 + kc + 9],     qhF[ks][2], qlF[ks][2]);
        split_pack(Qs[(m0+g+8)*68 + kc+8], Qs[(m0+g+8)*68 + kc + 9],   qhF[ks][3], qlF[ks][3]);
    }

    // B-frag ldmatrix lane addressing (x2, lanes 0-15 effective)
    const int lrow = (lane & 7);
    const uint32_t lsel = (uint32_t)(((lane >> 3) & 1) * 16);

    // ---- S = Q K^T over 16 K tiles ----
    for (int kt = 0; kt < 16; kt++) {
        const int st = kt & 1;
        // store K tile kt (from regs) as bf16 hi/lo
        {
            uint32_t hw0,hw1,hw2,hw3, lw0,lw1,lw2,lw3;
            split_pack(fa.x, fa.y, hw0, lw0);
            split_pack(fa.z, fa.w, hw1, lw1);
            split_pack(fb.x, fb.y, hw2, lw2);
            split_pack(fb.z, fb.w, hw3, lw3);
            char* dh = smem + AE_KV + st * AE_KVST + krow * 144 + kcol8 * 2;
            *(uint4*)dh            = make_uint4(hw0, hw1, hw2, hw3);
            *(uint4*)(dh + AE_TL)  = make_uint4(lw0, lw1, lw2, lw3);
        }
        if (kt < 15) {
            fa = *(const float4*)(Kb + (size_t)((kt+1)*64 + krow) * 64 + kcol8);
            fb = *(const float4*)(Kb + (size_t)((kt+1)*64 + krow) * 64 + kcol8 + 4);
        }
        __syncthreads();

        float accS[4] = {0.f, 0.f, 0.f, 0.f};
        const uint32_t kb_hi = sb + AE_KV + st * AE_KVST;
        #pragma unroll
        for (int ks = 0; ks < 4; ks++) {
            uint32_t addr = kb_hi + (uint32_t)(n0 + lrow) * 144 + ks * 32 + lsel;
            uint32_t bh[2], bl[2];
            LDSM_X2(bh[0], bh[1], addr);
            LDSM_X2(bl[0], bl[1], addr + AE_TL);
            mma_bf16(accS, qhF[ks], bh);
            mma_bf16(accS, qhF[ks], bl);
            mma_bf16(accS, qlF[ks], bh);
        }
        // store S tile
        int cbase = kt * 64 + n0 + 2 * t4;
        *(float2*)&Ssm[(m0+g)*SSTR + cbase]   = make_float2(accS[0], accS[1]);
        *(float2*)&Ssm[(m0+g+8)*SSTR + cbase] = make_float2(accS[2], accS[3]);
    }
    __syncthreads();

    // ---- softmax: 16 warps x 2 rows ----
    for (int rr = warp * 2; rr < warp * 2 + 2; rr++) {
        const int grow = r0 + rr;
        float* Srow = Ssm + rr * SSTR;
        const float* mrow = mask_s + (size_t)grow * 1024;
        float mx = -1e30f;
        for (int c = lane; c < 1024; c += 32) {
            float s = Srow[c] * 0.125f + mrow[c];
            Srow[c] = s;
            mx = fmaxf(mx, s);
        }
        #pragma unroll
        for (int o = 16; o > 0; o >>= 1) mx = fmaxf(mx, __shfl_xor_sync(0xffffffffu, mx, o));
        float sum = 0.f;
        for (int c = lane; c < 1024; c += 32) {
            float e = __expf(Srow[c] - mx);
            Srow[c] = e;
            sum += e;
        }
        #pragma unroll
        for (int o = 16; o > 0; o >>= 1) sum += __shfl_xor_sync(0xffffffffu, sum, o);
        float inv = 1.f / sum;
        float* arow = attn_s + ((size_t)(b * 8 + j) * 1024 + grow) * 1024;
        for (int c = lane; c < 1024; c += 32) {
            float p = Srow[c] * inv;
            Srow[c] = p;
            arow[c] = p;
        }
    }
    __syncthreads();

    // ---- O = P V over 16 V tiles ----
    float accO[4] = {0.f, 0.f, 0.f, 0.f};
    fa = *(const float4*)(Vb + (size_t)krow * 64 + kcol8);
    fb = *(const float4*)(Vb + (size_t)krow * 64 + kcol8 + 4);

    // A-frag (P) ldmatrix offset
    const int sub = lane >> 3, r8 = lane & 7;
    const uint32_t poff = (uint32_t)((m0 + r8 + (sub & 1) * 8) * 144 + (sub >> 1) * 16);
    const int vrow = (lane & 15);

    for (int kt = 0; kt < 16; kt++) {
        const int st = kt & 1;
        // store V tile kt (bf16 hi/lo)
        {
            uint32_t hw0,hw1,hw2,hw3, lw0,lw1,lw2,lw3;
            split_pack(fa.x, fa.y, hw0, lw0);
            split_pack(fa.z, fa.w, hw1, lw1);
            split_pack(fb.x, fb.y, hw2, lw2);
            split_pack(fb.z, fb.w, hw3, lw3);
            char* dh = smem + AE_KV + st * AE_KVST + krow * 144 + kcol8 * 2;
            *(uint4*)dh            = make_uint4(hw0, hw1, hw2, hw3);
            *(uint4*)(dh + AE_TL)  = make_uint4(lw0, lw1, lw2, lw3);
        }
        // convert P slice kt (32x64) -> bf16 hi/lo
        {
            float4 pv = *(const float4*)&Ssm[pr * SSTR + kt * 64 + pc];
            uint32_t h0, h1, l0, l1;
            split_pack(pv.x, pv.y, h0, l0);
            split_pack(pv.z, pv.w, h1, l1);
            char* dp = smem + AE_P + st * AE_PST + pr * 144 + pc * 2;
            *(uint2*)dp            = make_uint2(h0, h1);
            *(uint2*)(dp + AE_PTL) = make_uint2(l0, l1);
        }
        if (kt < 15) {
            fa = *(const float4*)(Vb + (size_t)((kt+1)*64 + krow) * 64 + kcol8);
            fb = *(const float4*)(Vb + (size_t)((kt+1)*64 + krow) * 64 + kcol8 + 4);
        }
        __syncthreads();

        const uint32_t pb_hi = sb + AE_P + st * AE_PST;
        const uint32_t vb_hi = sb + AE_KV + st * AE_KVST;
        #pragma unroll
        for (int ks = 0; ks < 4; ks++) {
            uint32_t ph[4], pl[4];
            LDSM_X4(ph[0], ph[1], ph[2], ph[3], pb_hi + poff + ks * 32);
            LDSM_X4(pl[0], pl[1], pl[2], pl[3], pb_hi + AE_PTL + poff + ks * 32);
            uint32_t vh[2], vl[2];
            uint32_t vaddr = vb_hi + (uint32_t)(ks * 16 + vrow) * 144 + n0 * 2;
            LDSM_X2_T(vh[0], vh[1], vaddr);
            LDSM_X2_T(vl[0], vl[1], vaddr + AE_TL);
            mma_bf16(accO, ph, vh);
            mma_bf16(accO, ph, vl);
            mma_bf16(accO, pl, vh);
        }
    }

    // store O tile
    {
        int c = j * 64 + n0 + 2 * t4;
        *(float2*)(out_cat + ((size_t)b * 1024 + r0 + m0 + g) * 1024 + c)     = make_float2(accO[0], accO[1]);
        *(float2*)(out_cat + ((size_t)b * 1024 + r0 + m0 + g + 8) * 1024 + c) = make_float2(accO[2], accO[3]);
    }
}

// ---------------------------------------------------------------------------
// Odd-head "feature" attention (unchanged).
// ---------------------------------------------------------------------------
#define SMEM_FEAT ((2*64*64 + 64*65) * 4)
__global__ __launch_bounds__(256) void attn_feat_k(
    const float* __restrict__ Qh, const float* __restrict__ Kh,
    const float* __restrict__ Vh, const float* __restrict__ mask_f,
    float* __restrict__ attn_f, float* __restrict__ out_cat)
{
    extern __shared__ float sm[];
    float* Qt  = sm;
    float* Kt  = Qt + 4096;
    float* Asm = Kt + 4096;

    const int jp = blockIdx.x, b = blockIdx.y;
    const int h = 2 * jp + 1;
    const int tid = threadIdx.x;
    const size_t headoff = (size_t)(b * 16 + h) * 1024 * 64;
    const float* Qb = Qh + headoff;
    const float* Kb = Kh + headoff;
    const float* Vb = Vh + headoff;

    const int m  = tid & 63;
    const int g4 = tid >> 6;

    float acc[16];
    #pragma unroll
    for (int i = 0; i < 16; i++) acc[i] = 0.f;

    for (int lt = 0; lt < 16; lt++) {
        __syncthreads();
        for (int i = tid; i < 1024; i += 256) {
            ((float4*)Qt)[i] = ((const float4*)(Qb + (size_t)lt * 4096))[i];
            ((float4*)Kt)[i] = ((const float4*)(Kb + (size_t)lt * 4096))[i];
        }
        __syncthreads();
        for (int ll = 0; ll < 64; ll++) {
            float kk = Kt[ll * 64 + m];
            #pragma unroll
            for (int i = 0; i < 16; i++)
                acc[i] = fmaf(Qt[ll * 64 + g4 + 4 * i], kk, acc[i]);
        }
    }
    __syncthreads();
    #pragma unroll
    for (int i = 0; i < 16; i++) {
        int n = g4 + 4 * i;
        Asm[n * 65 + m] = acc[i] * 0.125f + mask_f[n * 64 + m];
    }
    __syncthreads();

    const int warp = tid >> 5, lane = tid & 31;
    for (int n = warp * 8; n < warp * 8 + 8; n++) {
        float* row = Asm + n * 65;
        float a0 = row[lane], a1 = row[lane + 32];
        float mx = fmaxf(a0, a1);
        #pragma unroll
        for (int o = 16; o > 0; o >>= 1) mx = fmaxf(mx, __shfl_xor_sync(0xffffffffu, mx, o));
        float e0 = __expf(a0 - mx), e1 = __expf(a1 - mx);
        float s = e0 + e1;
        #pragma unroll
        for (int o = 16; o > 0; o >>= 1) s += __shfl_xor_sync(0xffffffffu, s, o);
        float inv = 1.f / s;
        e0 *= inv; e1 *= inv;
        row[lane] = e0; row[lane + 32] = e1;
        float* grow = attn_f + ((size_t)(b * 8 + jp) * 64 + n) * 64;
        grow[lane] = e0; grow[lane + 32] = e1;
    }
    __syncthreads();

    float* Vt = Qt;
    const int n2 = m;
    for (int lt = 0; lt < 16; lt++) {
        __syncthreads();
        for (int i = tid; i < 1024; i += 256)
            ((float4*)Vt)[i] = ((const float4*)(Vb + (size_t)lt * 4096))[i];
        __syncthreads();

        float accO[16];
        #pragma unroll
        for (int i = 0; i < 16; i++) accO[i] = 0.f;
        for (int mm = 0; mm < 64; mm++) {
            float aa = Asm[n2 * 65 + mm];
            #pragma unroll
            for (int i = 0; i < 16; i++)
                accO[i] = fmaf(Vt[(g4 + 4 * i) * 64 + mm], aa, accO[i]);
        }
        #pragma unroll
        for (int i = 0; i < 16; i++) {
            int ll = g4 + 4 * i;
            out_cat[((size_t)b * 1024 + lt * 64 + ll) * 1024 + (8 + jp) * 64 + n2] = accO[i];
        }
    }
}

// ---------------------------------------------------------------------------
extern "C" void kernel_launch(void* const* d_in, const int* in_sizes, int n_in,
                              void* d_out, int out_size)
{
    const float* q      = (const float*)d_in[0];
    const float* k      = (const float*)d_in[1];
    const float* v      = (const float*)d_in[2];
    const float* mask_s = (const float*)d_in[3];
    const float* mask_f = (const float*)d_in[4];
    const float* Wq     = (const float*)d_in[5];
    const float* Wk     = (const float*)d_in[6];
    const float* Wv     = (const float*)d_in[7];
    const float* Wo     = (const float*)d_in[8];

    float* out    = (float*)d_out;
    float* attn_s = out + OUT_ELEMS;
    float* attn_f = attn_s + ATTNS_ELEMS;

    float *qh, *kh, *vh, *cat;
    __nv_bfloat16 *ahi, *alo, *whi, *wlo;
    cudaGetSymbolAddress((void**)&qh,  g_qh);
    cudaGetSymbolAddress((void**)&kh,  g_kh);
    cudaGetSymbolAddress((void**)&vh,  g_vh);
    cudaGetSymbolAddress((void**)&cat, g_cat);
    cudaGetSymbolAddress((void**)&ahi, g_ahi);
    cudaGetSymbolAddress((void**)&alo, g_alo);
    cudaGetSymbolAddress((void**)&whi, g_whi);
    cudaGetSymbolAddress((void**)&wlo, g_wlo);

    cudaFuncSetAttribute(attn_even_k, cudaFuncAttributeMaxDynamicSharedMemorySize, SMEM_EVEN);
    cudaFuncSetAttribute(attn_feat_k, cudaFuncAttributeMaxDynamicSharedMemorySize, SMEM_FEAT);
    cudaFuncSetAttribute(gemm_lm_k<0>, cudaFuncAttributeMaxDynamicSharedMemorySize, GSMEM);
    cudaFuncSetAttribute(gemm_lm_k<1>, cudaFuncAttributeMaxDynamicSharedMemorySize, GSMEM);

    dim3 ggrid(DIMn / 128, (Bn * Ln) / 128);
    dim3 sgrid(OUT_ELEMS / (256 * 4));
    dim3 wgrid(32, 32), wblk(32, 8);

    // Q projection
    split_a_k<<<sgrid, 256>>>(q, ahi, alo);
    split_w_k<<<wgrid, wblk>>>(Wq, whi, wlo);
    gemm_lm_k<1><<<ggrid, 256, GSMEM>>>(ahi, alo, whi, wlo, qh);
    // K projection
    split_a_k<<<sgrid, 256>>>(k, ahi, alo);
    split_w_k<<<wgrid, wblk>>>(Wk, whi, wlo);
    gemm_lm_k<1><<<ggrid, 256, GSMEM>>>(ahi, alo, whi, wlo, kh);
    // V projection
    split_a_k<<<sgrid, 256>>>(v, ahi, alo);
    split_w_k<<<wgrid, wblk>>>(Wv, whi, wlo);
    gemm_lm_k<1><<<ggrid, 256, GSMEM>>>(ahi, alo, whi, wlo, vh);

    // Attention
    attn_even_k<<<dim3(32, 8, 16), 512, SMEM_EVEN>>>(qh, kh, vh, mask_s, attn_s, cat);
    attn_feat_k<<<dim3(8, 16), 256, SMEM_FEAT>>>(qh, kh, vh, mask_f, attn_f, cat);

    // Output projection
    split_a_k<<<sgrid, 256>>>(cat, ahi, alo);
    split_w_k<<<wgrid, wblk>>>(Wo, whi, wlo);
    gemm_lm_k<0><<<ggrid, 256, GSMEM>>>(ahi, alo, whi, wlo, out);
}